// round 10
// baseline (speedup 1.0000x reference)
#include <cuda_runtime.h>

#define NN 1024
#define DD 128

// ---------------------------------------------------------------------------
// Device scratch (allocation-free)
// ---------------------------------------------------------------------------
__device__ float g_PIB [NN * DD];   // pi + b1, row-major (for ci)
__device__ float g_PIBT[DD * NN];   // pi + b1, transposed [d][i]
__device__ float g_PJ  [NN * DD];   // pj, row-major (for cj)
__device__ float g_PJT [DD * NN];   // pj, transposed [d][j]
__device__ float g_W2H [DD];        // 0.5 * W2
__device__ float g_ci  [NN];
__device__ float g_cj  [NN];

// ---------------------------------------------------------------------------
// f32x2 packed helpers (sm_103a)
// ---------------------------------------------------------------------------
__device__ __forceinline__ unsigned long long pack2(float lo, float hi) {
    unsigned long long r;
    asm("mov.b64 %0, {%1, %2};" : "=l"(r) : "f"(lo), "f"(hi));
    return r;
}
__device__ __forceinline__ void unpack2(unsigned long long v, float& lo, float& hi) {
    asm("mov.b64 {%0, %1}, %2;" : "=f"(lo), "=f"(hi) : "l"(v));
}
__device__ __forceinline__ unsigned long long add2(unsigned long long a, unsigned long long b) {
    unsigned long long r;
    asm("add.rn.f32x2 %0, %1, %2;" : "=l"(r) : "l"(a), "l"(b));
    return r;
}
__device__ __forceinline__ unsigned long long fma2(unsigned long long a, unsigned long long b,
                                                   unsigned long long c) {
    unsigned long long r;
    asm("fma.rn.f32x2 %0, %1, %2, %3;" : "=l"(r) : "l"(a), "l"(b), "l"(c));
    return r;
}
#define ABS2_MASK 0x7FFFFFFF7FFFFFFFULL

// ---------------------------------------------------------------------------
// Kernel A: prep (unchanged from round 9 — proven).
// 128 blocks x 512 threads. dc = tid&255 (concat column), h = tid>>8,
// 4 rows each, scalar W1 loads unroll 16.
// ---------------------------------------------------------------------------
__global__ void __launch_bounds__(512, 1) prep_kernel(
    const float* __restrict__ z, const float* __restrict__ W1,
    const float* __restrict__ b1, const float* __restrict__ W2)
{
    __shared__ float zs[8][DD];
    const int tid = threadIdx.x;         // 0..511
    const int dc  = tid & 255;           // concat output column
    const int h   = tid >> 8;            // row half (0/1) -> rows 4h..4h+3
    const int i0  = blockIdx.x * 8;

    if (blockIdx.x == 0 && tid < DD) g_W2H[tid] = 0.5f * W2[tid];

    if (tid < 256)
        ((float4*)zs)[tid] = ((const float4*)(z + i0 * DD))[tid];
    __syncthreads();

    const bool is_pi = (dc < DD);
    const int  d     = is_pi ? dc : dc - DD;
    const float* wcol = is_pi ? (W1 + d) : (W1 + DD * DD + d);
    const int r0 = 4 * h;

    float acc[4] = {0.f, 0.f, 0.f, 0.f};

    #pragma unroll 16
    for (int k = 0; k < DD; k++) {
        const float w = __ldg(&wcol[k * DD]);
        #pragma unroll
        for (int ii = 0; ii < 4; ii++)
            acc[ii] = fmaf(zs[r0 + ii][k], w, acc[ii]);
    }

    if (is_pi) {
        const float bb = __ldg(&b1[d]);
        #pragma unroll
        for (int ii = 0; ii < 4; ii++) acc[ii] += bb;
        #pragma unroll
        for (int ii = 0; ii < 4; ii++)
            g_PIB[(i0 + r0 + ii) * DD + d] = acc[ii];     // coalesced across dc
        *(float4*)&g_PIBT[d * NN + i0 + r0] = *(float4*)&acc[0];
    } else {
        #pragma unroll
        for (int ii = 0; ii < 4; ii++)
            g_PJ[(i0 + r0 + ii) * DD + d] = acc[ii];
        *(float4*)&g_PJT[d * NN + i0 + r0] = *(float4*)&acc[0];
    }
}

// ---------------------------------------------------------------------------
// Kernel B: ci[i] = g_PIB[i,:] . g_W2H ; cj[j] = g_PJ[j,:] . g_W2H
// ---------------------------------------------------------------------------
__global__ void __launch_bounds__(256) cicj_kernel()
{
    const int warp = blockIdx.x * 8 + (threadIdx.x >> 5);
    const int lane = threadIdx.x & 31;
    const bool is_ci = warp < NN;
    const int  row   = is_ci ? warp : warp - NN;
    const float* src = is_ci ? (g_PIB + row * DD) : (g_PJ + row * DD);

    float4 v = *(const float4*)(src + lane * 4);
    float4 w = *(const float4*)(g_W2H + lane * 4);
    float s = v.x * w.x + v.y * w.y + v.z * w.z + v.w * w.w;
    #pragma unroll
    for (int off = 16; off; off >>= 1)
        s += __shfl_down_sync(0xFFFFFFFFu, s, off);
    if (lane == 0) {
        if (is_ci) g_ci[row] = s; else g_cj[row] = s;
    }
}

// ---------------------------------------------------------------------------
// Kernel C (v4): single pass, no combine.
// q[i,j] = ci[i] + cj[j] + sum_d w'_d |pi[d,i] + pj[d,j]| + b2
// Tile 64i x 32j, 256 threads (16x16): ty -> 4 i (2 f32x2 packs), tx -> 2 j.
// pj staged in smem PRE-BROADCAST-PACKED {v,v} -> zero pack MOVs in the loop.
// Per element-d: 1 fma-lane + 1 alu-lane (balanced pipes).
// Grid 512 blocks, ~3 blocks/SM resident (smem 65KB, dynamic).
// ---------------------------------------------------------------------------
__global__ void __launch_bounds__(256, 3) pair_kernel(
    const float* __restrict__ b2, float* __restrict__ out)
{
    extern __shared__ char sm_raw[];
    float*              pisT = (float*)sm_raw;                  // [128][64]  32 KB
    unsigned long long* pjp  = (unsigned long long*)(sm_raw + 32768); // [128][32] 32 KB
    unsigned long long* w2p  = (unsigned long long*)(sm_raw + 65536); // [128]     1 KB

    const int tx  = threadIdx.x;                // 0..15 -> 2 j
    const int ty  = threadIdx.y;                // 0..15 -> 4 i
    const int tid = ty * 16 + tx;
    const int ib  = blockIdx.y * 64;
    const int jb  = blockIdx.x * 32;

    // Stage pi tile [128 d][64 i]: 2048 float4, coalesced, conflict-free
    #pragma unroll
    for (int it = 0; it < 8; it++) {
        const int idx = tid + it * 256;
        const int d = idx >> 4;
        const int q = idx & 15;
        *(float4*)&pisT[d * 64 + q * 4] =
            *(const float4*)&g_PIBT[d * NN + ib + q * 4];
    }
    // Stage pj tile [128 d][32 j] broadcast-packed {v,v}
    #pragma unroll
    for (int it = 0; it < 16; it++) {
        const int idx = tid + it * 256;
        const int d  = idx >> 5;
        const int js = idx & 31;
        const float v = g_PJT[d * NN + jb + js];
        pjp[d * 32 + js] = pack2(v, v);
    }
    if (tid < DD) {
        const float w = g_W2H[tid];
        w2p[tid] = pack2(w, w);
    }
    __syncthreads();

    const int i0 = ty * 4;                      // local i base (2 packs)
    const int j0 = tx * 2;                      // local j base

    unsigned long long acc[2][2];               // [i-pack][j]
    acc[0][0] = acc[0][1] = acc[1][0] = acc[1][1] = 0ULL;

    #pragma unroll 8
    for (int d = 0; d < DD; d++) {
        const ulonglong2 aA = *(const ulonglong2*)&pisT[d * 64 + i0];  // 2 i-packs
        const ulonglong2 bB = *(const ulonglong2*)&pjp [d * 32 + j0];  // 2 packed j
        const unsigned long long wd = w2p[d];                          // broadcast

        unsigned long long t;
        t = add2(aA.x, bB.x) & ABS2_MASK;  acc[0][0] = fma2(wd, t, acc[0][0]);
        t = add2(aA.x, bB.y) & ABS2_MASK;  acc[0][1] = fma2(wd, t, acc[0][1]);
        t = add2(aA.y, bB.x) & ABS2_MASK;  acc[1][0] = fma2(wd, t, acc[1][0]);
        t = add2(aA.y, bB.y) & ABS2_MASK;  acc[1][1] = fma2(wd, t, acc[1][1]);
    }

    // Epilogue: 4 rows x 2 cols; add rank-1 terms + b2
    const int ig = ib + i0;
    const int jg = jb + j0;
    const float4 civ = *(const float4*)&g_ci[ig];
    const float2 cjv = *(const float2*)&g_cj[jg];
    const float  bb  = __ldg(b2);
    const float  cia[4] = { civ.x, civ.y, civ.z, civ.w };

    float v[4][2];                              // [local i][j]
    #pragma unroll
    for (int p = 0; p < 2; p++)
        #pragma unroll
        for (int j = 0; j < 2; j++) {
            float lo, hi;
            unpack2(acc[p][j], lo, hi);
            v[2 * p][j]     = lo;
            v[2 * p + 1][j] = hi;
        }

    #pragma unroll
    for (int r = 0; r < 4; r++) {
        const float base = cia[r] + bb;
        float2 o;
        o.x = v[r][0] + cjv.x + base;
        o.y = v[r][1] + cjv.y + base;
        *(float2*)&out[(ig + r) * NN + jg] = o;
    }
}

// ---------------------------------------------------------------------------
// metadata order: z [1024*128], W1 [256*128], b1 [128], W2 [128], b2 [1]
// output: float32 [1024*1024]
// ---------------------------------------------------------------------------
extern "C" void kernel_launch(void* const* d_in, const int* in_sizes, int n_in,
                              void* d_out, int out_size)
{
    const float* z  = (const float*)d_in[0];
    const float* W1 = (const float*)d_in[1];
    const float* b1 = (const float*)d_in[2];
    const float* W2 = (const float*)d_in[3];
    const float* b2 = (const float*)d_in[4];
    float* out = (float*)d_out;

    const int smem_bytes = 65536 + 1024;
    cudaFuncSetAttribute(pair_kernel,
                         cudaFuncAttributeMaxDynamicSharedMemorySize, smem_bytes);

    prep_kernel<<<NN / 8, 512>>>(z, W1, b1, W2);
    cicj_kernel<<<256, 256>>>();

    dim3 blk(16, 16);
    dim3 grd(NN / 32, NN / 64);
    pair_kernel<<<grd, blk, smem_bytes>>>(b2, out);
}